// round 5
// baseline (speedup 1.0000x reference)
#include <cuda_runtime.h>
#include <cstdint>

// NolinerSEM: per-expert MLP. For each (b, e):
//   h[32] = leaky( W1[e] (32x90) @ x[b,e,:] (90) + b1[e] )
//   o     = leaky( dot(h, W2[e]) + b2[e] )
// out[b, e] = o.   B = 32768, E = 90, H = 32.
//
// Strategy: per expert e this is a GEMM (B x 90) @ (90 x 32). Each CTA handles
// (expert e, 128-row block) using mma.sync.m16n8k8 tf32 with fp32 accumulation.
// Inputs converted with cvt.rna.tf32.f32 (round-to-nearest) at smem staging to
// keep relative error ~2e-4 (well under the 1e-3 gate).

namespace {
constexpr int Ee  = 90;
constexpr int Hh  = 32;
constexpr int STR = 100;   // smem row stride in floats; 100 % 32 == 4 -> conflict-free frag loads
constexpr int MT  = 128;   // rows (batch) per CTA
constexpr int KSTEPS = 12; // K padded 90 -> 96, 12 steps of k=8
constexpr float NEG = 0.33f;
}

__device__ __forceinline__ uint32_t f2tf32(float x) {
    uint32_t u;
    asm("cvt.rna.tf32.f32 %0, %1;" : "=r"(u) : "f"(x));
    return u;
}

__device__ __forceinline__ float lk(float v) { return v >= 0.f ? v : NEG * v; }

__device__ __forceinline__ void mma8(float c[4], const uint32_t a[4], const uint32_t b[2]) {
    asm volatile(
        "mma.sync.aligned.m16n8k8.row.col.f32.tf32.tf32.f32 "
        "{%0,%1,%2,%3}, {%4,%5,%6,%7}, {%8,%9}, {%0,%1,%2,%3};"
        : "+f"(c[0]), "+f"(c[1]), "+f"(c[2]), "+f"(c[3])
        : "r"(a[0]), "r"(a[1]), "r"(a[2]), "r"(a[3]), "r"(b[0]), "r"(b[1]));
}

__global__ void __launch_bounds__(128) sem_kernel(
    const float* __restrict__ x, const float* __restrict__ W1,
    const float* __restrict__ b1, const float* __restrict__ W2,
    const float* __restrict__ b2, float* __restrict__ out)
{
    extern __shared__ float smem[];
    float* Xs  = smem;            // [MT][STR] tf32 bits
    float* Ws  = Xs + MT * STR;   // [Hh][STR] tf32 bits, layout [n][k]
    float* b1s = Ws + Hh * STR;   // [32]
    float* w2s = b1s + Hh;        // [32]

    const int e       = blockIdx.x % Ee;
    const int rowBase = (blockIdx.x / Ee) * MT;
    const int tid  = threadIdx.x;
    const int lane = tid & 31;
    const int w    = tid >> 5;

    // ---- stage W1[e] (32 x 90, f contiguous) as Ws[n][k], tf32, zero-pad k 90..95 ----
    const float* W1e = W1 + (size_t)e * (Hh * Ee);
    for (int idx = tid; idx < Hh * Ee; idx += 128) {
        int n = idx / Ee, k = idx - n * Ee;
        ((uint32_t*)Ws)[n * STR + k] = f2tf32(W1e[idx]);
    }
    if (tid < Hh) {
        #pragma unroll
        for (int k = Ee; k < 96; ++k) Ws[tid * STR + k] = 0.f;
        b1s[tid] = b1[e * Hh + tid];
        w2s[tid] = W2[e * Hh + tid];   // W2 shape (E,1,H)
    }

    // ---- stage X tile: 128 rows of 90 floats, x[b,0,e,:] ----
    for (int r = w; r < MT; r += 4) {
        const float* xr = x + (size_t)(rowBase + r) * (Ee * Ee) + e * Ee;
        float v0 = xr[lane];
        float v1 = xr[lane + 32];
        float v2 = (lane < 26) ? xr[lane + 64] : 0.f;   // lanes 26..31 -> zero pad k=90..95
        uint32_t* xsr = (uint32_t*)(Xs + r * STR);
        xsr[lane]      = f2tf32(v0);
        xsr[lane + 32] = f2tf32(v1);
        xsr[lane + 64] = f2tf32(v2);
    }
    __syncthreads();

    // ---- per-warp 32(m) x 32(n) tile over K=96 via m16n8k8 tf32 ----
    const int g = lane >> 2, t = lane & 3;
    float c[2][4][4];
    #pragma unroll
    for (int mi = 0; mi < 2; ++mi)
        #pragma unroll
        for (int ni = 0; ni < 4; ++ni)
            #pragma unroll
            for (int j = 0; j < 4; ++j) c[mi][ni][j] = 0.f;

    const uint32_t* Xw = (const uint32_t*)(Xs + (w * 32) * STR);
    const uint32_t* Wb = (const uint32_t*)Ws;

    #pragma unroll
    for (int ks = 0; ks < KSTEPS; ++ks) {
        const int kb = ks * 8;
        uint32_t a[2][4], bf[4][2];
        #pragma unroll
        for (int mi = 0; mi < 2; ++mi) {
            const uint32_t* ap = Xw + (mi * 16 + g) * STR + kb;
            a[mi][0] = ap[t];                // A[g     ][t]
            a[mi][1] = ap[8 * STR + t];      // A[g + 8 ][t]
            a[mi][2] = ap[t + 4];            // A[g     ][t+4]
            a[mi][3] = ap[8 * STR + t + 4];  // A[g + 8 ][t+4]
        }
        #pragma unroll
        for (int ni = 0; ni < 4; ++ni) {
            const uint32_t* bp = Wb + (ni * 8 + g) * STR + kb;
            bf[ni][0] = bp[t];               // B[k=t  ][n=g]  (Ws is [n][k])
            bf[ni][1] = bp[t + 4];           // B[k=t+4][n=g]
        }
        #pragma unroll
        for (int mi = 0; mi < 2; ++mi)
            #pragma unroll
            for (int ni = 0; ni < 4; ++ni)
                mma8(c[mi][ni], a[mi], bf[ni]);
    }

    // ---- epilogue: leaky(c + b1) -> dot with w2 -> quad reduce -> leaky(+b2) ----
    float p[2][2] = {{0.f, 0.f}, {0.f, 0.f}};   // [mi][row g vs g+8]
    #pragma unroll
    for (int ni = 0; ni < 4; ++ni) {
        const int c0 = ni * 8 + 2 * t;
        const float bb0 = b1s[c0], bb1 = b1s[c0 + 1];
        const float ww0 = w2s[c0], ww1 = w2s[c0 + 1];
        #pragma unroll
        for (int mi = 0; mi < 2; ++mi) {
            p[mi][0] += lk(c[mi][ni][0] + bb0) * ww0 + lk(c[mi][ni][1] + bb1) * ww1;
            p[mi][1] += lk(c[mi][ni][2] + bb0) * ww0 + lk(c[mi][ni][3] + bb1) * ww1;
        }
    }
    #pragma unroll
    for (int mi = 0; mi < 2; ++mi)
        #pragma unroll
        for (int j = 0; j < 2; ++j) {
            float v = p[mi][j];
            v += __shfl_xor_sync(0xffffffffu, v, 1);
            v += __shfl_xor_sync(0xffffffffu, v, 2);
            p[mi][j] = v;
        }
    if (t == 0) {
        const float bias2 = b2[e];   // b2 shape (E,1)
        #pragma unroll
        for (int mi = 0; mi < 2; ++mi)
            #pragma unroll
            for (int j = 0; j < 2; ++j) {
                int r = rowBase + w * 32 + mi * 16 + j * 8 + g;
                out[(size_t)r * Ee + e] = lk(p[mi][j] + bias2);
            }
    }
}

extern "C" void kernel_launch(void* const* d_in, const int* in_sizes, int n_in,
                              void* d_out, int out_size) {
    const float* x  = (const float*)d_in[0];
    const float* W1 = (const float*)d_in[1];
    const float* b1 = (const float*)d_in[2];
    const float* W2 = (const float*)d_in[3];
    const float* b2 = (const float*)d_in[4];
    float* out = (float*)d_out;

    const int B = in_sizes[0] / (Ee * Ee);           // 32768
    const int grid = (B / MT) * Ee;                  // 256 * 90 = 23040
    const size_t smem = (size_t)(MT * STR + Hh * STR + 2 * Hh) * sizeof(float); // 64256 B

    cudaFuncSetAttribute(sem_kernel, cudaFuncAttributeMaxDynamicSharedMemorySize, (int)smem);
    sem_kernel<<<grid, 128, smem>>>(x, W1, b1, W2, b2, out);
}

// round 7
// speedup vs baseline: 1.2718x; 1.2718x over previous
#include <cuda_runtime.h>
#include <cstdint>

// NolinerSEM: per-expert MLP. out[b,e] = leaky(dot(leaky(W1[e]@x[b,e,:]+b1[e]), W2[e]) + b2[e])
// B=32768, E=90, H=32.
//
// R6 (= R5 resubmit; prior bench was a container infra failure):
// cp.async (LDGSTS) staging of the X tile (raw fp32, 8B chunks) + 256 threads
// (8 warps x 16-row m-tiles). tf32 conversion moved to the consumer (cvt.rna on
// A fragments after LDS); W1 staged pre-converted to tf32.

namespace {
constexpr int Ee  = 90;
constexpr int Hh  = 32;
constexpr int STR = 100;   // smem row stride (floats); 100 % 32 == 4 -> conflict-free frags
constexpr int MT  = 128;   // batch rows per CTA
constexpr int KSTEPS = 12; // K padded 90 -> 96
constexpr int THREADS = 256;
constexpr float NEG = 0.33f;
constexpr int CHUNKS = MT * 45;   // 8B chunks in the X tile (45 per row)
}

__device__ __forceinline__ uint32_t f2tf32(float x) {
    uint32_t u;
    asm("cvt.rna.tf32.f32 %0, %1;" : "=r"(u) : "f"(x));
    return u;
}

__device__ __forceinline__ float lk(float v) { return v >= 0.f ? v : NEG * v; }

__device__ __forceinline__ uint32_t smem_u32(const void* p) {
    uint32_t a;
    asm("{ .reg .u64 t; cvta.to.shared.u64 t, %1; cvt.u32.u64 %0, t; }" : "=r"(a) : "l"(p));
    return a;
}

__device__ __forceinline__ void cpasync8(uint32_t saddr, const void* g) {
    asm volatile("cp.async.ca.shared.global [%0], [%1], 8;" :: "r"(saddr), "l"(g));
}

__device__ __forceinline__ void mma8(float c[4], const uint32_t a[4], const uint32_t b[2]) {
    asm volatile(
        "mma.sync.aligned.m16n8k8.row.col.f32.tf32.tf32.f32 "
        "{%0,%1,%2,%3}, {%4,%5,%6,%7}, {%8,%9}, {%0,%1,%2,%3};"
        : "+f"(c[0]), "+f"(c[1]), "+f"(c[2]), "+f"(c[3])
        : "r"(a[0]), "r"(a[1]), "r"(a[2]), "r"(a[3]), "r"(b[0]), "r"(b[1]));
}

__global__ void __launch_bounds__(THREADS, 3) sem_kernel(
    const float* __restrict__ x, const float* __restrict__ W1,
    const float* __restrict__ b1, const float* __restrict__ W2,
    const float* __restrict__ b2, float* __restrict__ out)
{
    extern __shared__ float smem[];
    float* Xs  = smem;            // [MT][STR] raw fp32
    float* Ws  = Xs + MT * STR;   // [Hh][STR] tf32 bits, [n][k]
    float* b1s = Ws + Hh * STR;   // [32]
    float* w2s = b1s + Hh;        // [32]

    const int e       = blockIdx.x % Ee;
    const int rowBase = (blockIdx.x / Ee) * MT;
    const int tid  = threadIdx.x;
    const int lane = tid & 31;
    const int w    = tid >> 5;

    // ---- issue cp.async for X tile: 45 8B chunks per row ----
    const float* xBase = x + (size_t)rowBase * (Ee * Ee) + e * Ee;
    const uint32_t xsBase = smem_u32(Xs);
    #pragma unroll 1
    for (int idx = tid; idx < CHUNKS; idx += THREADS) {
        const int r = idx / 45;
        const int c = idx - r * 45;           // 8B chunk within row
        cpasync8(xsBase + (uint32_t)(r * STR + c * 2) * 4u,
                 xBase + (size_t)r * (Ee * Ee) + c * 2);
    }
    asm volatile("cp.async.commit_group;");

    // ---- zero-pad X cols 90..95 (not covered by cp.async) ----
    for (int i = tid; i < MT * 6; i += THREADS) {
        const int r = i / 6, c = 90 + (i - (i / 6) * 6);
        Xs[r * STR + c] = 0.f;
    }

    // ---- stage W1[e] as tf32 [n][k], pad k 90..95; biases + w2 ----
    const float* W1e = W1 + (size_t)e * (Hh * Ee);
    for (int idx = tid; idx < Hh * Ee; idx += THREADS) {
        const int n = idx / Ee, k = idx - n * Ee;
        ((uint32_t*)Ws)[n * STR + k] = f2tf32(W1e[idx]);
    }
    if (tid < Hh) {
        #pragma unroll
        for (int k = Ee; k < 96; ++k) Ws[tid * STR + k] = 0.f;
        b1s[tid] = b1[e * Hh + tid];
        w2s[tid] = W2[e * Hh + tid];
    }

    asm volatile("cp.async.wait_group 0;");
    __syncthreads();

    // ---- per-warp 16(m) x 32(n) tile over K=96 via m16n8k8 tf32 ----
    const int g = lane >> 2, t = lane & 3;
    float c[4][4];
    #pragma unroll
    for (int ni = 0; ni < 4; ++ni)
        #pragma unroll
        for (int j = 0; j < 4; ++j) c[ni][j] = 0.f;

    const float*    Xw = Xs + (w * 16) * STR;
    const uint32_t* Wb = (const uint32_t*)Ws;

    #pragma unroll
    for (int ks = 0; ks < KSTEPS; ++ks) {
        const int kb = ks * 8;
        uint32_t a[4], bf[4][2];
        {
            const float* ap = Xw + g * STR + kb;
            a[0] = f2tf32(ap[t]);                // A[g   ][t]
            a[1] = f2tf32(ap[8 * STR + t]);      // A[g+8 ][t]
            a[2] = f2tf32(ap[t + 4]);            // A[g   ][t+4]
            a[3] = f2tf32(ap[8 * STR + t + 4]);  // A[g+8 ][t+4]
        }
        #pragma unroll
        for (int ni = 0; ni < 4; ++ni) {
            const uint32_t* bp = Wb + (ni * 8 + g) * STR + kb;
            bf[ni][0] = bp[t];
            bf[ni][1] = bp[t + 4];
        }
        #pragma unroll
        for (int ni = 0; ni < 4; ++ni)
            mma8(c[ni], a, bf[ni]);
    }

    // ---- epilogue: leaky(c+b1) . w2 -> quad reduce -> leaky(+b2) -> store ----
    float p[2] = {0.f, 0.f};    // rows g and g+8
    #pragma unroll
    for (int ni = 0; ni < 4; ++ni) {
        const int c0 = ni * 8 + 2 * t;
        const float bb0 = b1s[c0], bb1 = b1s[c0 + 1];
        const float ww0 = w2s[c0], ww1 = w2s[c0 + 1];
        p[0] += lk(c[ni][0] + bb0) * ww0 + lk(c[ni][1] + bb1) * ww1;
        p[1] += lk(c[ni][2] + bb0) * ww0 + lk(c[ni][3] + bb1) * ww1;
    }
    #pragma unroll
    for (int j = 0; j < 2; ++j) {
        float v = p[j];
        v += __shfl_xor_sync(0xffffffffu, v, 1);
        v += __shfl_xor_sync(0xffffffffu, v, 2);
        p[j] = v;
    }
    if (t == 0) {
        const float bias2 = b2[e];
        #pragma unroll
        for (int j = 0; j < 2; ++j) {
            const int r = rowBase + w * 16 + j * 8 + g;
            out[(size_t)r * Ee + e] = lk(p[j] + bias2);
        }
    }
}

extern "C" void kernel_launch(void* const* d_in, const int* in_sizes, int n_in,
                              void* d_out, int out_size) {
    const float* x  = (const float*)d_in[0];
    const float* W1 = (const float*)d_in[1];
    const float* b1 = (const float*)d_in[2];
    const float* W2 = (const float*)d_in[3];
    const float* b2 = (const float*)d_in[4];
    float* out = (float*)d_out;

    const int B = in_sizes[0] / (Ee * Ee);           // 32768
    const int grid = (B / MT) * Ee;                  // 23040
    const size_t smem = (size_t)(MT * STR + Hh * STR + 2 * Hh) * sizeof(float); // 64256 B

    cudaFuncSetAttribute(sem_kernel, cudaFuncAttributeMaxDynamicSharedMemorySize, (int)smem);
    sem_kernel<<<grid, THREADS, smem>>>(x, W1, b1, W2, b2, out);
}

// round 9
// speedup vs baseline: 1.2846x; 1.0101x over previous
#include <cuda_runtime.h>
#include <cstdint>

// NolinerSEM: per-expert MLP. out[b,e] = leaky(dot(leaky(W1[e]@x[b,e,:]+b1[e]), W2[e]) + b2[e])
// B=32768, E=90, H=32.
//
// R7: (1) K-relabeling so each mma thread's (k=t, k=t+4) slots map to ADJACENT
// natural columns (8ks+2t, 8ks+2t+1) -> all fragment loads become LDS.64 from
// the natural layout (mainloop LDS halved). Stride 104 keeps LDS.64 conflict-free.
// (2) Div-free warp-per-row staging loops (kills the IMAD/IADD div-by-45/90 chains
// that made alu the top pipe at 46.8%).

namespace {
constexpr int Ee  = 90;
constexpr int Hh  = 32;
constexpr int STR = 104;   // floats; (104*g + 2t) % 32 = 8g+2t -> conflict-free LDS.64
constexpr int MT  = 128;   // batch rows per CTA
constexpr int KSTEPS = 12; // K padded 90 -> 96
constexpr int THREADS = 256;
constexpr float NEG = 0.33f;
}

__device__ __forceinline__ uint32_t f2tf32(float x) {
    uint32_t u;
    asm("cvt.rna.tf32.f32 %0, %1;" : "=r"(u) : "f"(x));
    return u;
}

__device__ __forceinline__ float lk(float v) { return v >= 0.f ? v : NEG * v; }

__device__ __forceinline__ uint32_t smem_u32(const void* p) {
    uint32_t a;
    asm("{ .reg .u64 t; cvta.to.shared.u64 t, %1; cvt.u32.u64 %0, t; }" : "=r"(a) : "l"(p));
    return a;
}

__device__ __forceinline__ void cpasync8(uint32_t saddr, const void* g) {
    asm volatile("cp.async.ca.shared.global [%0], [%1], 8;" :: "r"(saddr), "l"(g));
}

__device__ __forceinline__ void mma8(float c[4], const uint32_t a[4], const uint32_t b[2]) {
    asm volatile(
        "mma.sync.aligned.m16n8k8.row.col.f32.tf32.tf32.f32 "
        "{%0,%1,%2,%3}, {%4,%5,%6,%7}, {%8,%9}, {%0,%1,%2,%3};"
        : "+f"(c[0]), "+f"(c[1]), "+f"(c[2]), "+f"(c[3])
        : "r"(a[0]), "r"(a[1]), "r"(a[2]), "r"(a[3]), "r"(b[0]), "r"(b[1]));
}

__global__ void __launch_bounds__(THREADS, 3) sem_kernel(
    const float* __restrict__ x, const float* __restrict__ W1,
    const float* __restrict__ b1, const float* __restrict__ W2,
    const float* __restrict__ b2, float* __restrict__ out)
{
    extern __shared__ float smem[];
    float* Xs  = smem;            // [MT][STR] raw fp32, natural column order
    float* Ws  = Xs + MT * STR;   // [Hh][STR] tf32 bits, natural [n][k]
    float* b1s = Ws + Hh * STR;   // [32]
    float* w2s = b1s + Hh;        // [32]

    const int e       = blockIdx.x % Ee;
    const int rowBase = (blockIdx.x / Ee) * MT;
    const int tid  = threadIdx.x;
    const int lane = tid & 31;
    const int w    = tid >> 5;

    // ---- X staging: warp w stages rows {w, w+8, ...}; lane = 8B chunk. Div-free. ----
    {
        const float* xRow = x + (size_t)(rowBase + w) * (Ee * Ee) + e * Ee;
        uint32_t sRow = smem_u32(Xs) + (uint32_t)(w * STR) * 4u;
        #pragma unroll 1
        for (int i = 0; i < MT / 8; ++i) {
            cpasync8(sRow + (uint32_t)lane * 8u, xRow + lane * 2);            // cols 0..63
            if (lane < 13)
                cpasync8(sRow + (32u + lane) * 8u, xRow + 64 + lane * 2);     // cols 64..89
            xRow += 8 * (Ee * Ee);
            sRow += 8u * STR * 4u;
        }
    }
    asm volatile("cp.async.commit_group;");

    // ---- zero-pad X cols 90..95 (idle lanes 13..15 pattern, one pass) ----
    if (lane >= 13 && lane < 16) {
        float* zr = Xs + w * STR + 64 + lane * 2;   // cols 90,92,94 pairs
        #pragma unroll 1
        for (int i = 0; i < MT / 8; ++i) {
            *(float2*)zr = make_float2(0.f, 0.f);
            zr += 8 * STR;
        }
    }

    // ---- W1 staging: warp w stages n = {w, w+8, w+16, w+24}; vectorized, div-free ----
    {
        const float* wRow = W1 + (size_t)e * (Hh * Ee) + w * Ee;
        uint32_t* wsRow = (uint32_t*)(Ws + w * STR);
        #pragma unroll
        for (int j = 0; j < 4; ++j) {
            float2 v = *(const float2*)(wRow + lane * 2);
            ((uint2*)wsRow)[lane] = make_uint2(f2tf32(v.x), f2tf32(v.y));
            if (lane < 13) {
                float2 v2 = *(const float2*)(wRow + 64 + lane * 2);
                *(uint2*)(wsRow + 64 + lane * 2) = make_uint2(f2tf32(v2.x), f2tf32(v2.y));
            } else if (lane < 16) {
                *(uint2*)(wsRow + 64 + lane * 2) = make_uint2(0u, 0u);        // cols 90..95
            }
            wRow  += 8 * Ee;
            wsRow += 8 * STR;
        }
    }
    if (tid < Hh) {
        b1s[tid] = b1[e * Hh + tid];
        w2s[tid] = W2[e * Hh + tid];
    }

    asm volatile("cp.async.wait_group 0;");
    __syncthreads();

    // ---- per-warp 16(m) x 32(n) over K=96; all fragment loads are LDS.64 ----
    // K-relabel: in kstep ks, thread t's slots (k=t, k=t+4) hold natural cols
    // (8ks+2t, 8ks+2t+1) for BOTH A and B -> consistent dot product.
    const int g = lane >> 2, t = lane & 3;
    float c[4][4];
    #pragma unroll
    for (int ni = 0; ni < 4; ++ni)
        #pragma unroll
        for (int j = 0; j < 4; ++j) c[ni][j] = 0.f;

    const float* aRow0 = Xs + (w * 16 + g) * STR + 2 * t;  // row g
    const float* aRow1 = aRow0 + 8 * STR;                  // row g+8
    const uint32_t* bBase = (const uint32_t*)Ws + g * STR + 2 * t;

    #pragma unroll
    for (int ks = 0; ks < KSTEPS; ++ks) {
        const int kb = ks * 8;
        float2 A0 = *(const float2*)(aRow0 + kb);
        float2 A1 = *(const float2*)(aRow1 + kb);
        uint32_t a[4];
        a[0] = f2tf32(A0.x);   // slot k=t    <- col 8ks+2t
        a[1] = f2tf32(A1.x);
        a[2] = f2tf32(A0.y);   // slot k=t+4  <- col 8ks+2t+1
        a[3] = f2tf32(A1.y);
        #pragma unroll
        for (int ni = 0; ni < 4; ++ni) {
            uint2 B = *(const uint2*)(bBase + ni * 8 * STR + kb);
            uint32_t bf[2] = { B.x, B.y };
            mma8(c[ni], a, bf);
        }
    }

    // ---- epilogue: leaky(c+b1) . w2 -> quad reduce -> leaky(+b2) -> store ----
    float p[2] = {0.f, 0.f};    // rows g and g+8
    #pragma unroll
    for (int ni = 0; ni < 4; ++ni) {
        const int c0 = ni * 8 + 2 * t;
        const float bb0 = b1s[c0], bb1 = b1s[c0 + 1];
        const float ww0 = w2s[c0], ww1 = w2s[c0 + 1];
        p[0] += lk(c[ni][0] + bb0) * ww0 + lk(c[ni][1] + bb1) * ww1;
        p[1] += lk(c[ni][2] + bb0) * ww0 + lk(c[ni][3] + bb1) * ww1;
    }
    #pragma unroll
    for (int j = 0; j < 2; ++j) {
        float v = p[j];
        v += __shfl_xor_sync(0xffffffffu, v, 1);
        v += __shfl_xor_sync(0xffffffffu, v, 2);
        p[j] = v;
    }
    if (t == 0) {
        const float bias2 = b2[e];
        #pragma unroll
        for (int j = 0; j < 2; ++j) {
            const int r = rowBase + w * 16 + j * 8 + g;
            out[(size_t)r * Ee + e] = lk(p[j] + bias2);
        }
    }
}

extern "C" void kernel_launch(void* const* d_in, const int* in_sizes, int n_in,
                              void* d_out, int out_size) {
    const float* x  = (const float*)d_in[0];
    const float* W1 = (const float*)d_in[1];
    const float* b1 = (const float*)d_in[2];
    const float* W2 = (const float*)d_in[3];
    const float* b2 = (const float*)d_in[4];
    float* out = (float*)d_out;

    const int B = in_sizes[0] / (Ee * Ee);           // 32768
    const int grid = (B / MT) * Ee;                  // 23040
    const size_t smem = (size_t)(MT * STR + Hh * STR + 2 * Hh) * sizeof(float); // 66816 B

    cudaFuncSetAttribute(sem_kernel, cudaFuncAttributeMaxDynamicSharedMemorySize, (int)smem);
    sem_kernel<<<grid, THREADS, smem>>>(x, W1, b1, W2, b2, out);
}

// round 13
// speedup vs baseline: 1.4072x; 1.0955x over previous
#include <cuda_runtime.h>
#include <cstdint>

// NolinerSEM: per-expert MLP. out[b,e] = leaky(dot(leaky(W1[e]@x[b,e,:]+b1[e]), W2[e]) + b2[e])
// B=32768, E=90, H=32.
//
// R9: double-buffered tile pipeline. Each CTA = (expert e, 512 rows) = 8 tiles of
// 64 rows. cp.async for tile i+1 overlaps compute of tile i (wait_group 1), so
// DRAM latency is exposed once per CTA, not once per tile. W1 staged once per CTA.
// 8 warps = 4 m-tiles x 2 n-halves; layer-2 partials combined via smem.

namespace {
constexpr int Ee  = 90;
constexpr int Hh  = 32;
constexpr int STR = 104;   // floats; LDS.64 conflict-free
constexpr int MT  = 64;    // rows per tile
constexpr int T   = 8;     // tiles per CTA
constexpr int KSTEPS = 12; // K padded 90 -> 96
constexpr int THREADS = 256;
constexpr float NEG = 0.33f;
constexpr int XBUF = MT * STR;  // floats per X buffer
}

__device__ __forceinline__ uint32_t f2tf32(float x) {
    uint32_t u;
    asm("cvt.rna.tf32.f32 %0, %1;" : "=r"(u) : "f"(x));
    return u;
}

__device__ __forceinline__ float lk(float v) { return v >= 0.f ? v : NEG * v; }

__device__ __forceinline__ uint32_t smem_u32(const void* p) {
    uint32_t a;
    asm("{ .reg .u64 t; cvta.to.shared.u64 t, %1; cvt.u32.u64 %0, t; }" : "=r"(a) : "l"(p));
    return a;
}

__device__ __forceinline__ void cpasync8(uint32_t saddr, const void* g) {
    asm volatile("cp.async.ca.shared.global [%0], [%1], 8;" :: "r"(saddr), "l"(g));
}

__device__ __forceinline__ void mma8(float c[4], const uint32_t a[4], uint32_t b0, uint32_t b1) {
    asm volatile(
        "mma.sync.aligned.m16n8k8.row.col.f32.tf32.tf32.f32 "
        "{%0,%1,%2,%3}, {%4,%5,%6,%7}, {%8,%9}, {%0,%1,%2,%3};"
        : "+f"(c[0]), "+f"(c[1]), "+f"(c[2]), "+f"(c[3])
        : "r"(a[0]), "r"(a[1]), "r"(a[2]), "r"(a[3]), "r"(b0), "r"(b1));
}

__global__ void __launch_bounds__(THREADS, 3) sem_kernel(
    const float* __restrict__ x, const float* __restrict__ W1,
    const float* __restrict__ b1, const float* __restrict__ W2,
    const float* __restrict__ b2, float* __restrict__ out, int G)
{
    extern __shared__ float smem[];
    float* Xs   = smem;                 // [2][MT][STR] raw fp32
    float* Ws   = Xs + 2 * XBUF;        // [Hh][STR] tf32 bits, natural [n][k]
    float* b1s  = Ws + Hh * STR;        // [32]
    float* w2s  = b1s + Hh;             // [32]
    float* part = w2s + Hh;             // [MT] layer-2 partials (n-half 1)

    const int e    = blockIdx.x / G;
    const int grp  = blockIdx.x - e * G;
    const int row0 = grp * (MT * T);
    const int tid  = threadIdx.x;
    const int lane = tid & 31;
    const int w    = tid >> 5;
    const uint32_t xsBase = smem_u32(Xs);

    // ---- tile staging: warp w stages rows {w, w+8, ...} of tile t_idx; div-free ----
    auto stage = [&](int t_idx) {
        const int buf = t_idx & 1;
        const float* xRow = x + (size_t)(row0 + t_idx * MT + w) * (Ee * Ee) + e * Ee;
        uint32_t sRow = xsBase + (uint32_t)(buf * XBUF + w * STR) * 4u;
        #pragma unroll 1
        for (int i = 0; i < MT / 8; ++i) {
            cpasync8(sRow + (uint32_t)lane * 8u, xRow + lane * 2);           // cols 0..63
            if (lane < 13)
                cpasync8(sRow + (32u + lane) * 8u, xRow + 64 + lane * 2);    // cols 64..89
            xRow += 8 * (Ee * Ee);
            sRow += 8u * STR * 4u;
        }
    };

    // ---- prologue: stage tile 0, W1, biases; zero-pad cols 90..95 of both buffers ----
    stage(0);
    asm volatile("cp.async.commit_group;");

    {   // W1[e]: warp w stages n = {w, w+8, w+16, w+24}; vectorized, div-free
        const float* wRow = W1 + (size_t)e * (Hh * Ee) + w * Ee;
        uint32_t* wsRow = (uint32_t*)(Ws + w * STR);
        #pragma unroll
        for (int j = 0; j < 4; ++j) {
            float2 v = *(const float2*)(wRow + lane * 2);
            ((uint2*)wsRow)[lane] = make_uint2(f2tf32(v.x), f2tf32(v.y));
            if (lane < 13) {
                float2 v2 = *(const float2*)(wRow + 64 + lane * 2);
                *(uint2*)(wsRow + 64 + lane * 2) = make_uint2(f2tf32(v2.x), f2tf32(v2.y));
            } else if (lane < 16) {
                *(uint2*)(wsRow + 64 + lane * 2) = make_uint2(0u, 0u);       // pad 90..95
            }
            wRow  += 8 * Ee;
            wsRow += 8 * STR;
        }
    }
    if (tid < Hh) {
        b1s[tid] = b1[e * Hh + tid];
        w2s[tid] = W2[e * Hh + tid];
    }
    for (int idx = tid; idx < 2 * MT; idx += THREADS) {                      // X pads (one-time)
        float* zp = Xs + (idx >> 6) * XBUF + (idx & (MT - 1)) * STR + 90;
        #pragma unroll
        for (int j = 0; j < 3; ++j) ((float2*)zp)[j] = make_float2(0.f, 0.f);
    }
    const float bias2 = b2[e];

    // ---- warp roles: wm = m-tile (16 rows), wn = n-half (16 cols) ----
    const int g = lane >> 2, t = lane & 3;
    const int wm = w & 3, wn = w >> 2;
    const uint32_t* bBase = (const uint32_t*)Ws + (wn * 16 + g) * STR + 2 * t;

    // ---- pipelined tile loop ----
    #pragma unroll 1
    for (int i = 0; i < T; ++i) {
        if (i + 1 < T) {
            stage(i + 1);
            asm volatile("cp.async.commit_group;");
            asm volatile("cp.async.wait_group 1;");   // tile i complete; i+1 in flight
        } else {
            asm volatile("cp.async.wait_group 0;");
        }
        __syncthreads();   // tile i visible; also fences part[] reuse

        // -- compute: 16(m) x 16(n) per warp over K=96; all fragment loads LDS.64 --
        const float* aRow0 = Xs + (i & 1) * XBUF + (wm * 16 + g) * STR + 2 * t;
        const float* aRow1 = aRow0 + 8 * STR;
        float c[2][4];
        #pragma unroll
        for (int nl = 0; nl < 2; ++nl)
            #pragma unroll
            for (int j = 0; j < 4; ++j) c[nl][j] = 0.f;

        #pragma unroll
        for (int ks = 0; ks < KSTEPS; ++ks) {
            const int kb = ks * 8;
            float2 A0 = *(const float2*)(aRow0 + kb);
            float2 A1 = *(const float2*)(aRow1 + kb);
            uint32_t a[4];
            a[0] = f2tf32(A0.x);   // slot k=t    <- natural col 8ks+2t
            a[1] = f2tf32(A1.x);
            a[2] = f2tf32(A0.y);   // slot k=t+4  <- natural col 8ks+2t+1
            a[3] = f2tf32(A1.y);
            #pragma unroll
            for (int nl = 0; nl < 2; ++nl) {
                uint2 B = *(const uint2*)(bBase + nl * 8 * STR + kb);
                mma8(c[nl], a, B.x, B.y);
            }
        }

        // -- epilogue: leaky(c+b1) . w2 over this warp's 16 cols -> quad reduce --
        float p0 = 0.f, p1 = 0.f;      // rows g, g+8
        #pragma unroll
        for (int nl = 0; nl < 2; ++nl) {
            const int c0 = (wn * 2 + nl) * 8 + 2 * t;
            const float bb0 = b1s[c0], bb1 = b1s[c0 + 1];
            const float ww0 = w2s[c0], ww1 = w2s[c0 + 1];
            p0 += lk(c[nl][0] + bb0) * ww0 + lk(c[nl][1] + bb1) * ww1;
            p1 += lk(c[nl][2] + bb0) * ww0 + lk(c[nl][3] + bb1) * ww1;
        }
        p0 += __shfl_xor_sync(0xffffffffu, p0, 1);
        p0 += __shfl_xor_sync(0xffffffffu, p0, 2);
        p1 += __shfl_xor_sync(0xffffffffu, p1, 1);
        p1 += __shfl_xor_sync(0xffffffffu, p1, 2);

        if (t == 0 && wn == 1) {
            part[wm * 16 + g]     = p0;
            part[wm * 16 + 8 + g] = p1;
        }
        __syncthreads();   // partials visible; all reads of X buf[i&1] done
        if (t == 0 && wn == 0) {
            const int r = row0 + i * MT + wm * 16 + g;
            out[(size_t)r * Ee + e]       = lk(p0 + part[wm * 16 + g]     + bias2);
            out[(size_t)(r + 8) * Ee + e] = lk(p1 + part[wm * 16 + 8 + g] + bias2);
        }
    }
}

extern "C" void kernel_launch(void* const* d_in, const int* in_sizes, int n_in,
                              void* d_out, int out_size) {
    const float* x  = (const float*)d_in[0];
    const float* W1 = (const float*)d_in[1];
    const float* b1 = (const float*)d_in[2];
    const float* W2 = (const float*)d_in[3];
    const float* b2 = (const float*)d_in[4];
    float* out = (float*)d_out;

    const int B = in_sizes[0] / (Ee * Ee);           // 32768
    const int G = B / (MT * T);                      // 64 row-groups per expert
    const int grid = Ee * G;                         // 5760 CTAs
    const size_t smem = (size_t)(2 * XBUF + Hh * STR + 2 * Hh + MT) * sizeof(float); // 67072 B

    cudaFuncSetAttribute(sem_kernel, cudaFuncAttributeMaxDynamicSharedMemorySize, (int)smem);
    sem_kernel<<<grid, THREADS, smem>>>(x, W1, b1, W2, b2, out, G);
}